// round 6
// baseline (speedup 1.0000x reference)
#include <cuda_runtime.h>
#include <cstdint>

#define N_NODES 100000
#define N_EDGES 1600000
#define FEATS   64
#define PITCH_A 68
#define PITCH_B 68
#define NODES_PER_BLK 128
#define SMEM_BYTES ((NODES_PER_BLK * PITCH_A + 64 * PITCH_B) * 4)

// ---------------- device scratch (no allocs allowed) ----------------
__device__ int   g_deg[N_NODES];
__device__ int   g_rowptr[N_NODES + 1];
__device__ int   g_cursor[N_NODES];
__device__ int   g_col[N_EDGES];
__device__ float g_hA[N_NODES * FEATS];
__device__ float g_hB[N_NODES * FEATS];

// ---------------- packed f32x2 helpers ----------------
__device__ __forceinline__ void fma2(unsigned long long& d, unsigned long long a,
                                     unsigned long long b) {
    asm("fma.rn.f32x2 %0, %1, %2, %0;" : "+l"(d) : "l"(a), "l"(b));
}
__device__ __forceinline__ void add2(unsigned long long& d, unsigned long long b) {
    asm("add.rn.f32x2 %0, %0, %1;" : "+l"(d) : "l"(b));
}
__device__ __forceinline__ void mul2(unsigned long long& d, unsigned long long b) {
    asm("mul.rn.f32x2 %0, %0, %1;" : "+l"(d) : "l"(b));
}
__device__ __forceinline__ unsigned long long dup2(float x) {
    unsigned long long r;
    unsigned u = __float_as_uint(x);
    asm("mov.b64 %0, {%1, %1};" : "=l"(r) : "r"(u));
    return r;
}
__device__ __forceinline__ void unpack2(unsigned long long v, float& lo, float& hi) {
    unsigned a, b;
    asm("mov.b64 {%0, %1}, %2;" : "=r"(a), "=r"(b) : "l"(v));
    lo = __uint_as_float(a); hi = __uint_as_float(b);
}

// ---------------- CSR build ----------------
__global__ void hist_kernel(const int* __restrict__ dst) {
    int e = blockIdx.x * blockDim.x + threadIdx.x;
    if (e < N_EDGES) atomicAdd(&g_deg[dst[e]], 1);
}

// single-block exclusive scan of g_deg -> g_rowptr, g_cursor
__global__ void scan_kernel() {
    const int T = 1024;
    const int CH = (N_NODES + T - 1) / T;   // 98
    int tid = threadIdx.x;
    int beg = tid * CH;
    int end = min(N_NODES, beg + CH);

    int s = 0;
    for (int i = beg; i < end; i++) s += g_deg[i];

    __shared__ int sh[T];
    sh[tid] = s;
    __syncthreads();
    for (int d = 1; d < T; d <<= 1) {
        int v = (tid >= d) ? sh[tid - d] : 0;
        __syncthreads();
        sh[tid] += v;
        __syncthreads();
    }
    int run = sh[tid] - s;
    for (int i = beg; i < end; i++) {
        g_rowptr[i] = run;
        g_cursor[i] = run;
        run += g_deg[i];
    }
    if (tid == T - 1) g_rowptr[N_NODES] = sh[T - 1];
}

__global__ void scatter_kernel(const int* __restrict__ src,
                               const int* __restrict__ dst) {
    int e = blockIdx.x * blockDim.x + threadIdx.x;
    if (e < N_EDGES) {
        int pos = atomicAdd(&g_cursor[dst[e]], 1);
        g_col[pos] = src[e];
    }
}

// ---------------- fused layer: self-GEMM, in-smem aggregation, neigh-GEMM ----
// block: 128 nodes x 64 outs, 256 threads
// micro-tile: tx = tid&7 -> outs [8tx,8tx+8), ty = tid>>3 -> nodes [4ty,4ty+4)
template <bool RELU>
__global__ void __launch_bounds__(256) fused_layer_kernel(
        const float* __restrict__ hin,
        const float* __restrict__ Ws,
        const float* __restrict__ Wn,
        const float* __restrict__ bias,
        float* __restrict__ out) {
    extern __shared__ float smem[];
    float* A_s = smem;                               // [128][PITCH_A]
    float* B_s = smem + NODES_PER_BLK * PITCH_A;     // [64][PITCH_B]

    int tid = threadIdx.x;
    int node0 = blockIdx.x * NODES_PER_BLK;
    int tx = tid & 7;
    int ty = tid >> 3;
    int obase = tx * 8;

    // ---- load self tile + Ws ----
    #pragma unroll
    for (int i = 0; i < 8; i++) {
        int idx = tid + i * 256;
        int nr  = idx >> 4;
        int c4  = idx & 15;
        int gn  = node0 + nr;
        float4 v = make_float4(0.f, 0.f, 0.f, 0.f);
        if (gn < N_NODES) v = ((const float4*)hin)[(size_t)gn * 16 + c4];
        *(float4*)&A_s[nr * PITCH_A + c4 * 4] = v;
    }
    {
        int o   = tid & 63;
        int c4w = tid >> 6;
        #pragma unroll
        for (int i = 0; i < 4; i++) {
            int c4 = c4w + i * 4;
            float4 w = ((const float4*)Ws)[(size_t)o * 16 + c4];
            B_s[(c4 * 4 + 0) * PITCH_B + o] = w.x;
            B_s[(c4 * 4 + 1) * PITCH_B + o] = w.y;
            B_s[(c4 * 4 + 2) * PITCH_B + o] = w.z;
            B_s[(c4 * 4 + 3) * PITCH_B + o] = w.w;
        }
    }
    __syncthreads();

    // ---- acc = bias ----
    ulonglong2 bv01 = ((const ulonglong2*)bias)[2 * tx];
    ulonglong2 bv23 = ((const ulonglong2*)bias)[2 * tx + 1];
    unsigned long long acc[4][4];
    #pragma unroll
    for (int j = 0; j < 4; j++) {
        acc[j][0] = bv01.x; acc[j][1] = bv01.y;
        acc[j][2] = bv23.x; acc[j][3] = bv23.y;
    }

    // ---- compute self chunk ----
    #pragma unroll
    for (int k4 = 0; k4 < 16; k4++) {
        unsigned long long b[4][4];
        #pragma unroll
        for (int kk = 0; kk < 4; kk++) {
            const float* row = &B_s[(k4 * 4 + kk) * PITCH_B + obase];
            ulonglong2 b01 = *(const ulonglong2*)row;
            ulonglong2 b23 = *(const ulonglong2*)(row + 4);
            b[kk][0] = b01.x; b[kk][1] = b01.y;
            b[kk][2] = b23.x; b[kk][3] = b23.y;
        }
        #pragma unroll
        for (int j = 0; j < 4; j++) {
            float4 a = *(const float4*)&A_s[(4 * ty + j) * PITCH_A + k4 * 4];
            unsigned long long ad;
            ad = dup2(a.x);
            fma2(acc[j][0], ad, b[0][0]); fma2(acc[j][1], ad, b[0][1]);
            fma2(acc[j][2], ad, b[0][2]); fma2(acc[j][3], ad, b[0][3]);
            ad = dup2(a.y);
            fma2(acc[j][0], ad, b[1][0]); fma2(acc[j][1], ad, b[1][1]);
            fma2(acc[j][2], ad, b[1][2]); fma2(acc[j][3], ad, b[1][3]);
            ad = dup2(a.z);
            fma2(acc[j][0], ad, b[2][0]); fma2(acc[j][1], ad, b[2][1]);
            fma2(acc[j][2], ad, b[2][2]); fma2(acc[j][3], ad, b[2][3]);
            ad = dup2(a.w);
            fma2(acc[j][0], ad, b[3][0]); fma2(acc[j][1], ad, b[3][1]);
            fma2(acc[j][2], ad, b[3][2]); fma2(acc[j][3], ad, b[3][3]);
        }
    }
    __syncthreads();   // everyone done reading A_s (self) and B_s (Ws)

    // ---- load Wn into B_s; aggregate neighbor means into A_s ----
    {
        int o   = tid & 63;
        int c4w = tid >> 6;
        #pragma unroll
        for (int i = 0; i < 4; i++) {
            int c4 = c4w + i * 4;
            float4 w = ((const float4*)Wn)[(size_t)o * 16 + c4];
            B_s[(c4 * 4 + 0) * PITCH_B + o] = w.x;
            B_s[(c4 * 4 + 1) * PITCH_B + o] = w.y;
            B_s[(c4 * 4 + 2) * PITCH_B + o] = w.z;
            B_s[(c4 * 4 + 3) * PITCH_B + o] = w.w;
        }
    }
    {
        int warp = tid >> 5;
        int lane = tid & 31;
        int half = lane >> 4;
        int hl   = lane & 15;
        int slot = warp * 2 + half;            // 0..15
        unsigned mask = half ? 0xFFFF0000u : 0x0000FFFFu;
        const ulonglong2* h2 = (const ulonglong2*)hin;

        #pragma unroll 1
        for (int i = 0; i < NODES_PER_BLK / 16; i++) {   // 8 nodes per slot
            int nr = slot * 8 + i;
            int gn = node0 + nr;
            if (gn < N_NODES) {
                int beg = g_rowptr[gn];
                int end = g_rowptr[gn + 1];
                int cnt = end - beg;
                unsigned long long a0 = 0ull, a1 = 0ull;

                int e = beg;
                int nfull = (end - beg) >> 4;
                for (int bl = 0; bl < nfull; bl++, e += 16) {
                    int c = g_col[e + hl];
                    #pragma unroll
                    for (int j = 0; j < 16; j++) {
                        int s = __shfl_sync(mask, c, j, 16);
                        ulonglong2 v = h2[(size_t)s * 16 + hl];
                        add2(a0, v.x);
                        add2(a1, v.y);
                    }
                }
                int rem = end - e;
                if (rem) {
                    int c = (hl < rem) ? g_col[e + hl] : 0;
                    #pragma unroll
                    for (int j = 0; j < 16; j++) {
                        if (j < rem) {
                            int s = __shfl_sync(mask, c, j, 16);
                            ulonglong2 v = h2[(size_t)s * 16 + hl];
                            add2(a0, v.x);
                            add2(a1, v.y);
                        }
                    }
                }
                unsigned long long s2 = dup2(1.0f / (float)max(cnt, 1));
                mul2(a0, s2);
                mul2(a1, s2);
                ulonglong2 r; r.x = a0; r.y = a1;
                *(ulonglong2*)&A_s[nr * PITCH_A + hl * 4] = r;
            }
        }
    }
    __syncthreads();

    // ---- compute neigh chunk ----
    #pragma unroll
    for (int k4 = 0; k4 < 16; k4++) {
        unsigned long long b[4][4];
        #pragma unroll
        for (int kk = 0; kk < 4; kk++) {
            const float* row = &B_s[(k4 * 4 + kk) * PITCH_B + obase];
            ulonglong2 b01 = *(const ulonglong2*)row;
            ulonglong2 b23 = *(const ulonglong2*)(row + 4);
            b[kk][0] = b01.x; b[kk][1] = b01.y;
            b[kk][2] = b23.x; b[kk][3] = b23.y;
        }
        #pragma unroll
        for (int j = 0; j < 4; j++) {
            float4 a = *(const float4*)&A_s[(4 * ty + j) * PITCH_A + k4 * 4];
            unsigned long long ad;
            ad = dup2(a.x);
            fma2(acc[j][0], ad, b[0][0]); fma2(acc[j][1], ad, b[0][1]);
            fma2(acc[j][2], ad, b[0][2]); fma2(acc[j][3], ad, b[0][3]);
            ad = dup2(a.y);
            fma2(acc[j][0], ad, b[1][0]); fma2(acc[j][1], ad, b[1][1]);
            fma2(acc[j][2], ad, b[1][2]); fma2(acc[j][3], ad, b[1][3]);
            ad = dup2(a.z);
            fma2(acc[j][0], ad, b[2][0]); fma2(acc[j][1], ad, b[2][1]);
            fma2(acc[j][2], ad, b[2][2]); fma2(acc[j][3], ad, b[2][3]);
            ad = dup2(a.w);
            fma2(acc[j][0], ad, b[3][0]); fma2(acc[j][1], ad, b[3][1]);
            fma2(acc[j][2], ad, b[3][2]); fma2(acc[j][3], ad, b[3][3]);
        }
    }

    // ---- epilogue ----
    #pragma unroll
    for (int j = 0; j < 4; j++) {
        int gn = node0 + 4 * ty + j;
        if (gn < N_NODES) {
            float r[8];
            unpack2(acc[j][0], r[0], r[1]);
            unpack2(acc[j][1], r[2], r[3]);
            unpack2(acc[j][2], r[4], r[5]);
            unpack2(acc[j][3], r[6], r[7]);
            if (RELU) {
                #pragma unroll
                for (int o = 0; o < 8; o++) r[o] = (r[o] >= 0.f) ? r[o] : 0.01f * r[o];
            }
            float* op = out + (size_t)gn * 64 + obase;
            ((float4*)op)[0] = make_float4(r[0], r[1], r[2], r[3]);
            ((float4*)op)[1] = make_float4(r[4], r[5], r[6], r[7]);
        }
    }
}

// ---------------- launch ----------------
extern "C" void kernel_launch(void* const* d_in, const int* in_sizes, int n_in,
                              void* d_out, int out_size) {
    const float* in_feat = (const float*)d_in[0];
    const int*   src     = (const int*)d_in[1];
    const int*   dst     = (const int*)d_in[2];
    const float* w_s1    = (const float*)d_in[3];
    const float* w_n1    = (const float*)d_in[4];
    const float* b1      = (const float*)d_in[5];
    const float* w_s2    = (const float*)d_in[6];
    const float* w_n2    = (const float*)d_in[7];
    const float* b2      = (const float*)d_in[8];
    const float* w_s3    = (const float*)d_in[9];
    const float* w_n3    = (const float*)d_in[10];
    const float* b3      = (const float*)d_in[11];
    float* out = (float*)d_out;

    float* hA;  cudaGetSymbolAddress((void**)&hA, g_hA);
    float* hB;  cudaGetSymbolAddress((void**)&hB, g_hB);
    int*   deg; cudaGetSymbolAddress((void**)&deg, g_deg);

    // idempotent, called every launch (no static guards allowed)
    cudaFuncSetAttribute(fused_layer_kernel<true>,
                         cudaFuncAttributeMaxDynamicSharedMemorySize, SMEM_BYTES);
    cudaFuncSetAttribute(fused_layer_kernel<false>,
                         cudaFuncAttributeMaxDynamicSharedMemorySize, SMEM_BYTES);

    const int BLOCKS = (N_NODES + NODES_PER_BLK - 1) / NODES_PER_BLK;   // 782

    // --- CSR build (reused by all 3 layers) ---
    cudaMemsetAsync(deg, 0, N_NODES * sizeof(int));
    hist_kernel<<<N_EDGES / 256, 256>>>(dst);
    scan_kernel<<<1, 1024>>>();
    scatter_kernel<<<N_EDGES / 256, 256>>>(src, dst);

    // --- 3 fused layers (4th launch = profiled one) ---
    fused_layer_kernel<true><<<BLOCKS, 256, SMEM_BYTES>>>(in_feat, w_s1, w_n1, b1, hA);
    fused_layer_kernel<true><<<BLOCKS, 256, SMEM_BYTES>>>(hA, w_s2, w_n2, b2, hB);
    fused_layer_kernel<false><<<BLOCKS, 256, SMEM_BYTES>>>(hB, w_s3, w_n3, b3, out);
}

// round 8
// speedup vs baseline: 1.9833x; 1.9833x over previous
#include <cuda_runtime.h>
#include <cstdint>

#define N_NODES 100000
#define N_EDGES 1600000
#define FEATS   64
#define PITCH_A 68
#define PITCH_B 68
#define TILES   782          // ceil(100000/128)
#define GRID_GEMM 391        // each block does exactly 2 tiles
#define SMEM_GEMM ((2 * 64 * PITCH_B + 2 * 128 * PITCH_A) * 4)   // 104448 B

// ---------------- device scratch (no allocs allowed) ----------------
__device__ int   g_deg[N_NODES];
__device__ int   g_rowptr[N_NODES + 1];
__device__ int   g_cursor[N_NODES];
__device__ int   g_col[N_EDGES];
__device__ float g_hA[N_NODES * FEATS];
__device__ float g_hB[N_NODES * FEATS];
__device__ float g_neigh[N_NODES * FEATS];

// ---------------- packed f32x2 helpers ----------------
__device__ __forceinline__ void fma2(unsigned long long& d, unsigned long long a,
                                     unsigned long long b) {
    asm("fma.rn.f32x2 %0, %1, %2, %0;" : "+l"(d) : "l"(a), "l"(b));
}
__device__ __forceinline__ void add2(unsigned long long& d, unsigned long long b) {
    asm("add.rn.f32x2 %0, %0, %1;" : "+l"(d) : "l"(b));
}
__device__ __forceinline__ void mul2(unsigned long long& d, unsigned long long b) {
    asm("mul.rn.f32x2 %0, %0, %1;" : "+l"(d) : "l"(b));
}
__device__ __forceinline__ unsigned long long dup2(float x) {
    unsigned long long r;
    unsigned u = __float_as_uint(x);
    asm("mov.b64 %0, {%1, %1};" : "=l"(r) : "r"(u));
    return r;
}
__device__ __forceinline__ void unpack2(unsigned long long v, float& lo, float& hi) {
    unsigned a, b;
    asm("mov.b64 {%0, %1}, %2;" : "=r"(a), "=r"(b) : "l"(v));
    lo = __uint_as_float(a); hi = __uint_as_float(b);
}
__device__ __forceinline__ unsigned long long shfl_xor16_64(unsigned long long v) {
    unsigned lo, hi;
    asm("mov.b64 {%0, %1}, %2;" : "=r"(lo), "=r"(hi) : "l"(v));
    lo = __shfl_xor_sync(0xffffffffu, lo, 16);
    hi = __shfl_xor_sync(0xffffffffu, hi, 16);
    unsigned long long r;
    asm("mov.b64 %0, {%1, %2};" : "=l"(r) : "r"(lo), "r"(hi));
    return r;
}

// ---------------- cp.async helpers ----------------
__device__ __forceinline__ unsigned smem_u32(const void* p) {
    return (unsigned)__cvta_generic_to_shared(p);
}
__device__ __forceinline__ void cp16(unsigned s, const void* g) {
    asm volatile("cp.async.cg.shared.global [%0], [%1], 16;" :: "r"(s), "l"(g));
}
__device__ __forceinline__ void cp_commit() {
    asm volatile("cp.async.commit_group;" ::: "memory");
}
template <int N>
__device__ __forceinline__ void cp_wait() {
    asm volatile("cp.async.wait_group %0;" :: "n"(N) : "memory");
}

// ---------------- CSR build ----------------
__global__ void hist_kernel(const int* __restrict__ dst) {
    int e = blockIdx.x * blockDim.x + threadIdx.x;
    if (e < N_EDGES) atomicAdd(&g_deg[dst[e]], 1);
}

__global__ void scan_kernel() {
    const int T = 1024;
    const int CH = (N_NODES + T - 1) / T;   // 98
    int tid = threadIdx.x;
    int beg = tid * CH;
    int end = min(N_NODES, beg + CH);

    int s = 0;
    for (int i = beg; i < end; i++) s += g_deg[i];

    __shared__ int sh[T];
    sh[tid] = s;
    __syncthreads();
    for (int d = 1; d < T; d <<= 1) {
        int v = (tid >= d) ? sh[tid - d] : 0;
        __syncthreads();
        sh[tid] += v;
        __syncthreads();
    }
    int run = sh[tid] - s;
    for (int i = beg; i < end; i++) {
        g_rowptr[i] = run;
        g_cursor[i] = run;
        run += g_deg[i];
    }
    if (tid == T - 1) g_rowptr[N_NODES] = sh[T - 1];
}

__global__ void scatter_kernel(const int* __restrict__ src,
                               const int* __restrict__ dst) {
    int e = blockIdx.x * blockDim.x + threadIdx.x;
    if (e < N_EDGES) {
        int pos = atomicAdd(&g_cursor[dst[e]], 1);
        g_col[pos] = src[e];
    }
}

// ---------------- aggregation v2: full warp per node -------------------------
// lanes: half = lane>>4 picks neighbor parity slot, hl = lane&15 covers the 256B row.
// Each step processes 4 neighbors per warp (2 per half) -> MLP 4, short acc chains.
__global__ void __launch_bounds__(256) agg_kernel(const float* __restrict__ hin) {
    int warp = threadIdx.x >> 5;
    int lane = threadIdx.x & 31;
    int half = lane >> 4;
    int hl   = lane & 15;
    int n = blockIdx.x * 8 + warp;       // 12500 blocks * 8 warps

    int beg = g_rowptr[n];
    int cnt = g_rowptr[n + 1] - beg;

    const ulonglong2* h2 = (const ulonglong2*)hin;
    unsigned long long a0 = 0ull, a1 = 0ull;

    int done = 0;
    while (done < cnt) {
        int avail = min(32, cnt - done);                       // warp-uniform
        int c = (lane < avail) ? g_col[beg + done + lane] : 0;
        int quads = avail >> 2;
        #pragma unroll 2
        for (int j = 0; j < quads; j++) {
            int i0 = 4 * j + 2 * half;
            int s0 = __shfl_sync(0xffffffffu, c, i0);
            int s1 = __shfl_sync(0xffffffffu, c, i0 + 1);
            ulonglong2 v0 = h2[(size_t)s0 * 16 + hl];
            ulonglong2 v1 = h2[(size_t)s1 * 16 + hl];
            add2(a0, v0.x); add2(a1, v0.y);
            add2(a0, v1.x); add2(a1, v1.y);
        }
        int rem = avail & 3;
        if (rem) {                                             // warp-uniform branch
            int base = quads * 4;
            int i0 = base + 2 * half;
            int s0 = __shfl_sync(0xffffffffu, c, min(i0, avail - 1));
            int s1 = __shfl_sync(0xffffffffu, c, min(i0 + 1, avail - 1));
            if (i0 < avail) {
                ulonglong2 v = h2[(size_t)s0 * 16 + hl];
                add2(a0, v.x); add2(a1, v.y);
            }
            if (i0 + 1 < avail) {
                ulonglong2 v = h2[(size_t)s1 * 16 + hl];
                add2(a0, v.x); add2(a1, v.y);
            }
        }
        done += avail;
    }

    // combine the two halves' partial sums (butterfly over lane bit 4)
    unsigned long long t;
    t = shfl_xor16_64(a0); add2(a0, t);
    t = shfl_xor16_64(a1); add2(a1, t);

    unsigned long long s2 = dup2(1.0f / (float)max(cnt, 1));
    mul2(a0, s2);
    mul2(a1, s2);
    if (half == 0) {
        ulonglong2 r; r.x = a0; r.y = a1;
        ((ulonglong2*)g_neigh)[(size_t)n * 16 + hl] = r;
    }
}

// ---------------- GEMM compute chunk (FFMA2 core) ----------------------------
__device__ __forceinline__ void mm_chunk(const float* __restrict__ A_s,
                                         const float* __restrict__ B_s,
                                         int ty, int obase,
                                         unsigned long long acc[4][4]) {
    #pragma unroll
    for (int k4 = 0; k4 < 16; k4++) {
        unsigned long long b[4][4];
        #pragma unroll
        for (int kk = 0; kk < 4; kk++) {
            const float* row = &B_s[(k4 * 4 + kk) * PITCH_B + obase];
            ulonglong2 b01 = *(const ulonglong2*)row;
            ulonglong2 b23 = *(const ulonglong2*)(row + 4);
            b[kk][0] = b01.x; b[kk][1] = b01.y;
            b[kk][2] = b23.x; b[kk][3] = b23.y;
        }
        #pragma unroll
        for (int j = 0; j < 4; j++) {
            float4 a = *(const float4*)&A_s[(4 * ty + j) * PITCH_A + k4 * 4];
            unsigned long long ad;
            ad = dup2(a.x);
            fma2(acc[j][0], ad, b[0][0]); fma2(acc[j][1], ad, b[0][1]);
            fma2(acc[j][2], ad, b[0][2]); fma2(acc[j][3], ad, b[0][3]);
            ad = dup2(a.y);
            fma2(acc[j][0], ad, b[1][0]); fma2(acc[j][1], ad, b[1][1]);
            fma2(acc[j][2], ad, b[1][2]); fma2(acc[j][3], ad, b[1][3]);
            ad = dup2(a.z);
            fma2(acc[j][0], ad, b[2][0]); fma2(acc[j][1], ad, b[2][1]);
            fma2(acc[j][2], ad, b[2][2]); fma2(acc[j][3], ad, b[2][3]);
            ad = dup2(a.w);
            fma2(acc[j][0], ad, b[3][0]); fma2(acc[j][1], ad, b[3][1]);
            fma2(acc[j][2], ad, b[3][2]); fma2(acc[j][3], ad, b[3][3]);
        }
    }
}

__device__ __forceinline__ void load_tile_async(float* A_s, const float* src,
                                                int node0, int tid) {
    #pragma unroll
    for (int i = 0; i < 8; i++) {
        int idx = tid + i * 256;
        int nr  = idx >> 4;
        int c4  = idx & 15;
        int gn  = node0 + nr;
        if (gn < N_NODES)
            cp16(smem_u32(&A_s[nr * PITCH_A + c4 * 4]),
                 &src[(size_t)gn * 64 + c4 * 4]);
    }
}

// ---------------- persistent dual-GEMM: weights resident, cp.async pipeline ---
// grid = 391, each block handles tiles {b, b+391}; 128 nodes x 64 outs per tile.
template <bool RELU>
__global__ void __launch_bounds__(256) gemm_kernel(const float* __restrict__ hin,
                                                   const float* __restrict__ Ws,
                                                   const float* __restrict__ Wn,
                                                   const float* __restrict__ bias,
                                                   float* __restrict__ out) {
    extern __shared__ float smem[];
    float* WsT = smem;                        // [64][PITCH_B]
    float* WnT = WsT + 64 * PITCH_B;          // [64][PITCH_B]
    float* A0  = WnT + 64 * PITCH_B;          // [128][PITCH_A]
    float* A1  = A0 + 128 * PITCH_A;          // [128][PITCH_A]

    int tid = threadIdx.x;
    int tx = tid & 7;
    int ty = tid >> 3;
    int obase = tx * 8;

    // ---- load both weight tiles transposed (once per block) ----
    {
        int o   = tid & 63;
        int c4w = tid >> 6;
        #pragma unroll
        for (int i = 0; i < 4; i++) {
            int c4 = c4w + i * 4;
            float4 w1 = ((const float4*)Ws)[(size_t)o * 16 + c4];
            float4 w2 = ((const float4*)Wn)[(size_t)o * 16 + c4];
            WsT[(c4 * 4 + 0) * PITCH_B + o] = w1.x;
            WsT[(c4 * 4 + 1) * PITCH_B + o] = w1.y;
            WsT[(c4 * 4 + 2) * PITCH_B + o] = w1.z;
            WsT[(c4 * 4 + 3) * PITCH_B + o] = w1.w;
            WnT[(c4 * 4 + 0) * PITCH_B + o] = w2.x;
            WnT[(c4 * 4 + 1) * PITCH_B + o] = w2.y;
            WnT[(c4 * 4 + 2) * PITCH_B + o] = w2.z;
            WnT[(c4 * 4 + 3) * PITCH_B + o] = w2.w;
        }
    }

    ulonglong2 bv01 = ((const ulonglong2*)bias)[2 * tx];
    ulonglong2 bv23 = ((const ulonglong2*)bias)[2 * tx + 1];

    // ---- pipeline prologue: fetch first self tile ----
    int t = blockIdx.x;
    load_tile_async(A0, hin, t * 128, tid);
    cp_commit();

    #pragma unroll 1
    for (; t < TILES; t += GRID_GEMM) {
        int node0 = t * 128;

        cp_wait<0>();                       // A0 (self) ready; also covers weights on iter 0
        __syncthreads();

        load_tile_async(A1, g_neigh, node0, tid);   // neigh tile overlaps self compute
        cp_commit();

        unsigned long long acc[4][4];
        #pragma unroll
        for (int j = 0; j < 4; j++) {
            acc[j][0] = bv01.x; acc[j][1] = bv01.y;
            acc[j][2] = bv23.x; acc[j][3] = bv23.y;
        }

        mm_chunk(A0, WsT, ty, obase, acc);
        __syncthreads();                    // everyone done reading A0

        int t2 = t + GRID_GEMM;
        if (t2 < TILES) load_tile_async(A0, hin, t2 * 128, tid);   // prefetch next self
        cp_commit();                        // (possibly empty group)

        cp_wait<1>();                       // A1 (neigh) ready
        __syncthreads();

        mm_chunk(A1, WnT, ty, obase, acc);

        // ---- epilogue ----
        #pragma unroll
        for (int j = 0; j < 4; j++) {
            int gn = node0 + 4 * ty + j;
            if (gn < N_NODES) {
                float r[8];
                unpack2(acc[j][0], r[0], r[1]);
                unpack2(acc[j][1], r[2], r[3]);
                unpack2(acc[j][2], r[4], r[5]);
                unpack2(acc[j][3], r[6], r[7]);
                if (RELU) {
                    #pragma unroll
                    for (int o = 0; o < 8; o++) r[o] = (r[o] >= 0.f) ? r[o] : 0.01f * r[o];
                }
                float* op = out + (size_t)gn * 64 + obase;
                ((float4*)op)[0] = make_float4(r[0], r[1], r[2], r[3]);
                ((float4*)op)[1] = make_float4(r[4], r[5], r[6], r[7]);
            }
        }
    }
}

// ---------------- launch ----------------
extern "C" void kernel_launch(void* const* d_in, const int* in_sizes, int n_in,
                              void* d_out, int out_size) {
    const float* in_feat = (const float*)d_in[0];
    const int*   src     = (const int*)d_in[1];
    const int*   dst     = (const int*)d_in[2];
    const float* w_s1    = (const float*)d_in[3];
    const float* w_n1    = (const float*)d_in[4];
    const float* b1      = (const float*)d_in[5];
    const float* w_s2    = (const float*)d_in[6];
    const float* w_n2    = (const float*)d_in[7];
    const float* b2      = (const float*)d_in[8];
    const float* w_s3    = (const float*)d_in[9];
    const float* w_n3    = (const float*)d_in[10];
    const float* b3      = (const float*)d_in[11];
    float* out = (float*)d_out;

    float* hA;  cudaGetSymbolAddress((void**)&hA, g_hA);
    float* hB;  cudaGetSymbolAddress((void**)&hB, g_hB);
    int*   deg; cudaGetSymbolAddress((void**)&deg, g_deg);

    // idempotent (no static guards allowed)
    cudaFuncSetAttribute(gemm_kernel<true>,
                         cudaFuncAttributeMaxDynamicSharedMemorySize, SMEM_GEMM);
    cudaFuncSetAttribute(gemm_kernel<false>,
                         cudaFuncAttributeMaxDynamicSharedMemorySize, SMEM_GEMM);

    // --- CSR build --- (launch order keeps agg at profile index 3)
    cudaMemsetAsync(deg, 0, N_NODES * sizeof(int));
    hist_kernel<<<N_EDGES / 256, 256>>>(dst);
    scan_kernel<<<1, 1024>>>();
    scatter_kernel<<<N_EDGES / 256, 256>>>(src, dst);

    // --- layer 1 ---
    agg_kernel<<<N_NODES / 8, 256>>>(in_feat);
    gemm_kernel<true><<<GRID_GEMM, 256, SMEM_GEMM>>>(in_feat, w_s1, w_n1, b1, hA);
    // --- layer 2 ---
    agg_kernel<<<N_NODES / 8, 256>>>(hA);
    gemm_kernel<true><<<GRID_GEMM, 256, SMEM_GEMM>>>(hA, w_s2, w_n2, b2, hB);
    // --- layer 3 ---
    agg_kernel<<<N_NODES / 8, 256>>>(hB);
    gemm_kernel<false><<<GRID_GEMM, 256, SMEM_GEMM>>>(hB, w_s3, w_n3, b3, out);
}

// round 15
// speedup vs baseline: 2.8047x; 1.4141x over previous
#include <cuda_runtime.h>
#include <cstdint>

#define N_NODES 100000
#define N_EDGES 1600000
#define FEATS   64
#define PITCH_A 68
#define PITCH_B 68
#define SCAN_T  1024
#define SCAN_B  ((N_NODES + SCAN_T - 1) / SCAN_T)   // 98

// ---------------- device scratch (no allocs allowed) ----------------
__device__ int   g_deg[N_NODES];
__device__ int   g_rowptr[N_NODES + 1];
__device__ int   g_cursor[N_NODES];
__device__ int   g_col[N_EDGES];
__device__ int   g_bsum[128];
__device__ int   g_boff[128];
__device__ float g_hA[N_NODES * FEATS];
__device__ float g_hB[N_NODES * FEATS];
__device__ float g_neigh[N_NODES * FEATS];

// ---------------- packed f32x2 helpers ----------------
__device__ __forceinline__ void fma2(unsigned long long& d, unsigned long long a,
                                     unsigned long long b) {
    asm("fma.rn.f32x2 %0, %1, %2, %0;" : "+l"(d) : "l"(a), "l"(b));
}
__device__ __forceinline__ void add2(unsigned long long& d, unsigned long long b) {
    asm("add.rn.f32x2 %0, %0, %1;" : "+l"(d) : "l"(b));
}
__device__ __forceinline__ void mul2(unsigned long long& d, unsigned long long b) {
    asm("mul.rn.f32x2 %0, %0, %1;" : "+l"(d) : "l"(b));
}
__device__ __forceinline__ unsigned long long dup2(float x) {
    unsigned long long r;
    unsigned u = __float_as_uint(x);
    asm("mov.b64 %0, {%1, %1};" : "=l"(r) : "r"(u));
    return r;
}
__device__ __forceinline__ void unpack2(unsigned long long v, float& lo, float& hi) {
    unsigned a, b;
    asm("mov.b64 {%0, %1}, %2;" : "=r"(a), "=r"(b) : "l"(v));
    lo = __uint_as_float(a); hi = __uint_as_float(b);
}
__device__ __forceinline__ unsigned long long shfl_xor16_64(unsigned long long v) {
    unsigned lo, hi;
    asm("mov.b64 {%0, %1}, %2;" : "=r"(lo), "=r"(hi) : "l"(v));
    lo = __shfl_xor_sync(0xffffffffu, lo, 16);
    hi = __shfl_xor_sync(0xffffffffu, hi, 16);
    unsigned long long r;
    asm("mov.b64 %0, {%1, %2};" : "=l"(r) : "r"(lo), "r"(hi));
    return r;
}

// ---------------- CSR build ----------------
__global__ void hist_kernel(const int* __restrict__ dst) {
    int e = blockIdx.x * blockDim.x + threadIdx.x;
    if (e < N_EDGES) atomicAdd(&g_deg[dst[e]], 1);
}

__global__ void block_sum_kernel() {
    __shared__ int sh[SCAN_T];
    int i = blockIdx.x * SCAN_T + threadIdx.x;
    sh[threadIdx.x] = (i < N_NODES) ? g_deg[i] : 0;
    __syncthreads();
    for (int d = SCAN_T / 2; d > 0; d >>= 1) {
        if (threadIdx.x < d) sh[threadIdx.x] += sh[threadIdx.x + d];
        __syncthreads();
    }
    if (threadIdx.x == 0) g_bsum[blockIdx.x] = sh[0];
}

__global__ void scan_small_kernel() {
    __shared__ int sh[128];
    int tid = threadIdx.x;
    int v = (tid < SCAN_B) ? g_bsum[tid] : 0;
    sh[tid] = v;
    __syncthreads();
    for (int d = 1; d < 128; d <<= 1) {
        int t = (tid >= d) ? sh[tid - d] : 0;
        __syncthreads();
        sh[tid] += t;
        __syncthreads();
    }
    if (tid < SCAN_B) g_boff[tid] = sh[tid] - v;      // exclusive
    if (tid == SCAN_B - 1) g_rowptr[N_NODES] = sh[tid];
}

__global__ void fill_rowptr_kernel() {
    __shared__ int sh[SCAN_T];
    int tid = threadIdx.x;
    int i = blockIdx.x * SCAN_T + tid;
    int v = (i < N_NODES) ? g_deg[i] : 0;
    sh[tid] = v;
    __syncthreads();
    for (int d = 1; d < SCAN_T; d <<= 1) {
        int t = (tid >= d) ? sh[tid - d] : 0;
        __syncthreads();
        sh[tid] += t;
        __syncthreads();
    }
    if (i < N_NODES) {
        int ex = g_boff[blockIdx.x] + sh[tid] - v;
        g_rowptr[i] = ex;
        g_cursor[i] = ex;
    }
}

__global__ void scatter_kernel(const int* __restrict__ src,
                               const int* __restrict__ dst) {
    int e = blockIdx.x * blockDim.x + threadIdx.x;
    if (e < N_EDGES) {
        int pos = atomicAdd(&g_cursor[dst[e]], 1);
        g_col[pos] = src[e];
    }
}

// ---------------- aggregation v2: full warp per node, deeper MLP -------------
__global__ void __launch_bounds__(256) agg_kernel(const float* __restrict__ hin) {
    int warp = threadIdx.x >> 5;
    int lane = threadIdx.x & 31;
    int half = lane >> 4;
    int hl   = lane & 15;
    int n = blockIdx.x * 8 + warp;       // 12500 blocks * 8 warps

    int beg = g_rowptr[n];
    int cnt = g_rowptr[n + 1] - beg;

    const ulonglong2* h2 = (const ulonglong2*)hin;
    unsigned long long a0 = 0ull, a1 = 0ull;

    int done = 0;
    while (done < cnt) {
        int avail = min(32, cnt - done);                       // warp-uniform
        int c = (lane < avail) ? g_col[beg + done + lane] : 0;
        int quads = avail >> 2;
        #pragma unroll 4
        for (int j = 0; j < quads; j++) {
            int i0 = 4 * j + 2 * half;
            int s0 = __shfl_sync(0xffffffffu, c, i0);
            int s1 = __shfl_sync(0xffffffffu, c, i0 + 1);
            ulonglong2 v0 = h2[(size_t)s0 * 16 + hl];
            ulonglong2 v1 = h2[(size_t)s1 * 16 + hl];
            add2(a0, v0.x); add2(a1, v0.y);
            add2(a0, v1.x); add2(a1, v1.y);
        }
        int rem = avail & 3;
        if (rem) {                                             // warp-uniform branch
            int base = quads * 4;
            int i0 = base + 2 * half;
            int s0 = __shfl_sync(0xffffffffu, c, min(i0, avail - 1));
            int s1 = __shfl_sync(0xffffffffu, c, min(i0 + 1, avail - 1));
            if (i0 < avail) {
                ulonglong2 v = h2[(size_t)s0 * 16 + hl];
                add2(a0, v.x); add2(a1, v.y);
            }
            if (i0 + 1 < avail) {
                ulonglong2 v = h2[(size_t)s1 * 16 + hl];
                add2(a0, v.x); add2(a1, v.y);
            }
        }
        done += avail;
    }

    unsigned long long t;
    t = shfl_xor16_64(a0); add2(a0, t);
    t = shfl_xor16_64(a1); add2(a1, t);

    unsigned long long s2 = dup2(1.0f / (float)max(cnt, 1));
    mul2(a0, s2);
    mul2(a1, s2);
    if (half == 0) {
        ulonglong2 r; r.x = a0; r.y = a1;
        ((ulonglong2*)g_neigh)[(size_t)n * 16 + hl] = r;
    }
}

// ---------------- packed-FFMA2 dual GEMM + bias + leaky relu (R3 version) ----
// block tile: 128 nodes x 64 outs, 256 threads, micro-tile 4 nodes x 8 outs
template <bool RELU>
__global__ void __launch_bounds__(256) gemm_kernel(const float* __restrict__ hin,
                                                   const float* __restrict__ Ws,
                                                   const float* __restrict__ Wn,
                                                   const float* __restrict__ bias,
                                                   float* __restrict__ out) {
    __shared__ float A_s[128 * PITCH_A];   // [n][k] node-major, padded
    __shared__ float B_s[64 * PITCH_B];    // [k][o] transposed weights, padded

    int tid = threadIdx.x;
    int node0 = blockIdx.x * 128;
    int tx = tid & 7;
    int ty = tid >> 3;
    int obase = tx * 8;

    ulonglong2 bv01 = ((const ulonglong2*)bias)[2 * tx];
    ulonglong2 bv23 = ((const ulonglong2*)bias)[2 * tx + 1];
    unsigned long long acc[4][4];
    #pragma unroll
    for (int j = 0; j < 4; j++) {
        acc[j][0] = bv01.x; acc[j][1] = bv01.y;
        acc[j][2] = bv23.x; acc[j][3] = bv23.y;
    }

    #pragma unroll 1
    for (int chunk = 0; chunk < 2; chunk++) {
        const float* Aptr = (chunk == 0) ? hin : g_neigh;
        const float* Wptr = (chunk == 0) ? Ws  : Wn;

        if (chunk == 1) __syncthreads();

        #pragma unroll
        for (int i = 0; i < 8; i++) {
            int idx = tid + i * 256;
            int nr  = idx >> 4;
            int c4  = idx & 15;
            int gn  = node0 + nr;
            float4 v = make_float4(0.f, 0.f, 0.f, 0.f);
            if (gn < N_NODES)
                v = ((const float4*)Aptr)[(size_t)gn * 16 + c4];
            *(float4*)&A_s[nr * PITCH_A + c4 * 4] = v;
        }
        {
            int o   = tid & 63;
            int c4w = tid >> 6;
            #pragma unroll
            for (int i = 0; i < 4; i++) {
                int c4 = c4w + i * 4;
                float4 w = ((const float4*)Wptr)[(size_t)o * 16 + c4];
                B_s[(c4 * 4 + 0) * PITCH_B + o] = w.x;
                B_s[(c4 * 4 + 1) * PITCH_B + o] = w.y;
                B_s[(c4 * 4 + 2) * PITCH_B + o] = w.z;
                B_s[(c4 * 4 + 3) * PITCH_B + o] = w.w;
            }
        }
        __syncthreads();

        #pragma unroll 4
        for (int k4 = 0; k4 < 16; k4++) {
            unsigned long long b[4][4];
            #pragma unroll
            for (int kk = 0; kk < 4; kk++) {
                const float* row = &B_s[(k4 * 4 + kk) * PITCH_B + obase];
                ulonglong2 b01 = *(const ulonglong2*)row;
                ulonglong2 b23 = *(const ulonglong2*)(row + 4);
                b[kk][0] = b01.x; b[kk][1] = b01.y;
                b[kk][2] = b23.x; b[kk][3] = b23.y;
            }
            #pragma unroll
            for (int j = 0; j < 4; j++) {
                float4 a = *(const float4*)&A_s[(4 * ty + j) * PITCH_A + k4 * 4];
                unsigned long long ad;
                ad = dup2(a.x);
                fma2(acc[j][0], ad, b[0][0]); fma2(acc[j][1], ad, b[0][1]);
                fma2(acc[j][2], ad, b[0][2]); fma2(acc[j][3], ad, b[0][3]);
                ad = dup2(a.y);
                fma2(acc[j][0], ad, b[1][0]); fma2(acc[j][1], ad, b[1][1]);
                fma2(acc[j][2], ad, b[1][2]); fma2(acc[j][3], ad, b[1][3]);
                ad = dup2(a.z);
                fma2(acc[j][0], ad, b[2][0]); fma2(acc[j][1], ad, b[2][1]);
                fma2(acc[j][2], ad, b[2][2]); fma2(acc[j][3], ad, b[2][3]);
                ad = dup2(a.w);
                fma2(acc[j][0], ad, b[3][0]); fma2(acc[j][1], ad, b[3][1]);
                fma2(acc[j][2], ad, b[3][2]); fma2(acc[j][3], ad, b[3][3]);
            }
        }
    }

    #pragma unroll
    for (int j = 0; j < 4; j++) {
        int gn = node0 + 4 * ty + j;
        if (gn < N_NODES) {
            float r[8];
            unpack2(acc[j][0], r[0], r[1]);
            unpack2(acc[j][1], r[2], r[3]);
            unpack2(acc[j][2], r[4], r[5]);
            unpack2(acc[j][3], r[6], r[7]);
            if (RELU) {
                #pragma unroll
                for (int o = 0; o < 8; o++) r[o] = (r[o] >= 0.f) ? r[o] : 0.01f * r[o];
            }
            float* op = out + (size_t)gn * 64 + obase;
            ((float4*)op)[0] = make_float4(r[0], r[1], r[2], r[3]);
            ((float4*)op)[1] = make_float4(r[4], r[5], r[6], r[7]);
        }
    }
}

// ---------------- launch ----------------
extern "C" void kernel_launch(void* const* d_in, const int* in_sizes, int n_in,
                              void* d_out, int out_size) {
    const float* in_feat = (const float*)d_in[0];
    const int*   src     = (const int*)d_in[1];
    const int*   dst     = (const int*)d_in[2];
    const float* w_s1    = (const float*)d_in[3];
    const float* w_n1    = (const float*)d_in[4];
    const float* b1      = (const float*)d_in[5];
    const float* w_s2    = (const float*)d_in[6];
    const float* w_n2    = (const float*)d_in[7];
    const float* b2      = (const float*)d_in[8];
    const float* w_s3    = (const float*)d_in[9];
    const float* w_n3    = (const float*)d_in[10];
    const float* b3      = (const float*)d_in[11];
    float* out = (float*)d_out;

    float* hA;  cudaGetSymbolAddress((void**)&hA, g_hA);
    float* hB;  cudaGetSymbolAddress((void**)&hB, g_hB);
    int*   deg; cudaGetSymbolAddress((void**)&deg, g_deg);

    const int GEMM_BLOCKS = (N_NODES + 127) / 128;   // 782

    // --- CSR build (reused by all 3 layers) ---
    cudaMemsetAsync(deg, 0, N_NODES * sizeof(int));
    hist_kernel<<<N_EDGES / 256, 256>>>(dst);
    block_sum_kernel<<<SCAN_B, SCAN_T>>>();
    scan_small_kernel<<<1, 128>>>();
    fill_rowptr_kernel<<<SCAN_B, SCAN_T>>>();
    scatter_kernel<<<N_EDGES / 256, 256>>>(src, dst);

    // --- layer 1 ---
    agg_kernel<<<N_NODES / 8, 256>>>(in_feat);
    gemm_kernel<true><<<GEMM_BLOCKS, 256>>>(in_feat, w_s1, w_n1, b1, hA);
    // --- layer 2 ---
    agg_kernel<<<N_NODES / 8, 256>>>(hA);
    gemm_kernel<true><<<GEMM_BLOCKS, 256>>>(hA, w_s2, w_n2, b2, hB);
    // --- layer 3 ---
    agg_kernel<<<N_NODES / 8, 256>>>(hB);
    gemm_kernel<false><<<GEMM_BLOCKS, 256>>>(hB, w_s3, w_n3, b3, out);
}